// round 1
// baseline (speedup 1.0000x reference)
#include <cuda_runtime.h>

// Problem constants (fixed by the dataset)
#define B_    16
#define L_    256
#define D_    512
#define MELS_ 80
#define T_    3072
#define M_ENC (B_ * L_)   // 4096
#define M_DEC (B_ * T_)   // 49152

// Scratch (allocation-free rule: __device__ globals)
__device__ float g_enc[M_ENC * D_];   // relu'd encoder output, 8 MB
__device__ float g_dec[M_DEC * D_];   // relu'd decoder output, 100 MB
__device__ int   g_aidx[M_DEC];       // per-frame gather row index into g_enc, -1 = invalid

// ---------------------------------------------------------------------------
// Kernel 1: per-batch inclusive scan of durations + per-frame token search
// ---------------------------------------------------------------------------
__global__ void tok_kernel(const int* __restrict__ dur) {
    __shared__ int csum[L_];
    const int b   = blockIdx.x;
    const int tid = threadIdx.x;

    csum[tid] = dur[b * L_ + tid];
    __syncthreads();
    // Hillis-Steele inclusive scan over 256 entries
    for (int off = 1; off < L_; off <<= 1) {
        int x = (tid >= off) ? csum[tid - off] : 0;
        __syncthreads();
        csum[tid] += x;
        __syncthreads();
    }
    // tok = searchsorted(csum, t, side='right') = first i with csum[i] > t
    for (int t = tid; t < T_; t += blockDim.x) {
        int lo = 0, hi = L_;
        while (lo < hi) {
            int mid = (lo + hi) >> 1;
            if (csum[mid] > t) hi = mid; else lo = mid + 1;
        }
        g_aidx[b * T_ + t] = (lo < L_) ? (b * L_ + lo) : -1;
    }
}

// ---------------------------------------------------------------------------
// Kernel 2: enc = relu((emb[src] + pos) @ W_enc + b_enc)   M=4096 K=512 N=512
// 128x128 tile, BK=8, 256 threads, 8x8 micro-tile
// ---------------------------------------------------------------------------
__global__ __launch_bounds__(256) void enc_gemm(
    const int* __restrict__ src, const float* __restrict__ emb,
    const float* __restrict__ pos, const float* __restrict__ W,
    const float* __restrict__ bias)
{
    __shared__ float As[8][128];
    __shared__ float Bs[8][128];

    const int tid = threadIdx.x;
    const int m0  = blockIdx.y * 128;
    const int n0  = blockIdx.x * 128;
    const int ty = tid >> 4, tx = tid & 15;
    const int row0 = ty * 8, col0 = tx * 8;

    // A-tile load mapping: thread -> (row, 4-wide k segment)
    const int lrow = tid >> 1;
    const int kseg = (tid & 1) * 4;
    const int m    = m0 + lrow;
    const float* embrow = emb + (long)src[m] * D_;
    const float* posrow = pos + (long)(m % L_) * D_;

    // B-tile load mapping: thread -> (k row, 4-wide n segment)
    const int bk = tid >> 5;
    const int bn = (tid & 31) * 4;

    float acc[8][8] = {};

    for (int k0 = 0; k0 < D_; k0 += 8) {
        float4 e = *(const float4*)(embrow + k0 + kseg);
        float4 p = *(const float4*)(posrow + k0 + kseg);
        As[kseg + 0][lrow] = e.x + p.x;
        As[kseg + 1][lrow] = e.y + p.y;
        As[kseg + 2][lrow] = e.z + p.z;
        As[kseg + 3][lrow] = e.w + p.w;
        *(float4*)&Bs[bk][bn] = *(const float4*)(W + (long)(k0 + bk) * D_ + n0 + bn);
        __syncthreads();
#pragma unroll
        for (int kk = 0; kk < 8; kk++) {
            float a[8], b[8];
#pragma unroll
            for (int i = 0; i < 8; i++) a[i] = As[kk][row0 + i];
#pragma unroll
            for (int j = 0; j < 8; j++) b[j] = Bs[kk][col0 + j];
#pragma unroll
            for (int i = 0; i < 8; i++)
#pragma unroll
                for (int j = 0; j < 8; j++) acc[i][j] += a[i] * b[j];
        }
        __syncthreads();
    }
#pragma unroll
    for (int i = 0; i < 8; i++) {
        const int mm = m0 + row0 + i;
#pragma unroll
        for (int j = 0; j < 8; j++) {
            const int nn = n0 + col0 + j;
            float v = acc[i][j] + bias[nn];
            g_enc[(long)mm * D_ + nn] = v > 0.f ? v : 0.f;
        }
    }
}

// ---------------------------------------------------------------------------
// Kernel 3: duration head  dur_pred[m] = enc[m] . W_dur + b_dur
// ---------------------------------------------------------------------------
__global__ void dur_kernel(const float* __restrict__ Wd,
                           const float* __restrict__ bd,
                           float* __restrict__ out)
{
    const int m    = blockIdx.x * 8 + threadIdx.y;
    const int lane = threadIdx.x;
    float s = 0.f;
    for (int k = lane; k < D_; k += 32) s += g_enc[(long)m * D_ + k] * Wd[k];
#pragma unroll
    for (int o = 16; o; o >>= 1) s += __shfl_xor_sync(0xffffffffu, s, o);
    if (lane == 0) out[m] = s + bd[0];
}

// ---------------------------------------------------------------------------
// Kernel 4: dec = relu(gather(enc, aidx) @ W_dec + b_dec)  M=49152 K=512 N=512
// ---------------------------------------------------------------------------
__global__ __launch_bounds__(256) void dec_gemm(
    const float* __restrict__ W, const float* __restrict__ bias)
{
    __shared__ float As[8][128];
    __shared__ float Bs[8][128];

    const int tid = threadIdx.x;
    const int m0  = blockIdx.y * 128;
    const int n0  = blockIdx.x * 128;
    const int ty = tid >> 4, tx = tid & 15;
    const int row0 = ty * 8, col0 = tx * 8;

    const int lrow = tid >> 1;
    const int kseg = (tid & 1) * 4;
    const int aidx = g_aidx[m0 + lrow];
    const float* arow = (aidx >= 0) ? (g_enc + (long)aidx * D_) : nullptr;

    const int bk = tid >> 5;
    const int bn = (tid & 31) * 4;

    float acc[8][8] = {};

    for (int k0 = 0; k0 < D_; k0 += 8) {
        float4 av = make_float4(0.f, 0.f, 0.f, 0.f);
        if (arow) av = *(const float4*)(arow + k0 + kseg);
        As[kseg + 0][lrow] = av.x;
        As[kseg + 1][lrow] = av.y;
        As[kseg + 2][lrow] = av.z;
        As[kseg + 3][lrow] = av.w;
        *(float4*)&Bs[bk][bn] = *(const float4*)(W + (long)(k0 + bk) * D_ + n0 + bn);
        __syncthreads();
#pragma unroll
        for (int kk = 0; kk < 8; kk++) {
            float a[8], b[8];
#pragma unroll
            for (int i = 0; i < 8; i++) a[i] = As[kk][row0 + i];
#pragma unroll
            for (int j = 0; j < 8; j++) b[j] = Bs[kk][col0 + j];
#pragma unroll
            for (int i = 0; i < 8; i++)
#pragma unroll
                for (int j = 0; j < 8; j++) acc[i][j] += a[i] * b[j];
        }
        __syncthreads();
    }
#pragma unroll
    for (int i = 0; i < 8; i++) {
        const long mm = m0 + row0 + i;
#pragma unroll
        for (int j = 0; j < 8; j++) {
            const int nn = n0 + col0 + j;
            float v = acc[i][j] + bias[nn];
            g_dec[mm * D_ + nn] = v > 0.f ? v : 0.f;
        }
    }
}

// ---------------------------------------------------------------------------
// Kernel 5: mel[b, n, t] = (dec @ W_gen + b_gen) transposed  M=49152 K=512 N=80
// 128x80 tile, 160 threads (16x10), 8x8 micro-tile
// ---------------------------------------------------------------------------
__global__ __launch_bounds__(160) void gen_gemm(
    const float* __restrict__ W, const float* __restrict__ bias,
    float* __restrict__ mel)
{
    __shared__ float As[8][128];
    __shared__ float Bs[8][80];

    const int tid = threadIdx.x;
    const int m0  = blockIdx.y * 128;
    const int ty = tid / 10, tx = tid % 10;
    const int row0 = ty * 8, col0 = tx * 8;

    float acc[8][8] = {};

    for (int k0 = 0; k0 < D_; k0 += 8) {
        // A tile: 128 rows x 8 k = 256 float4 items, strided over 160 threads
        for (int it = tid; it < 256; it += 160) {
            const int r  = it >> 1;
            const int ks = (it & 1) * 4;
            float4 av = *(const float4*)(g_dec + (long)(m0 + r) * D_ + k0 + ks);
            As[ks + 0][r] = av.x;
            As[ks + 1][r] = av.y;
            As[ks + 2][r] = av.z;
            As[ks + 3][r] = av.w;
        }
        // B tile: 8 k x 80 n = 160 float4 items
        {
            const int r = tid / 20;
            const int c = (tid % 20) * 4;
            *(float4*)&Bs[r][c] = *(const float4*)(W + (long)(k0 + r) * MELS_ + c);
        }
        __syncthreads();
#pragma unroll
        for (int kk = 0; kk < 8; kk++) {
            float a[8], b[8];
#pragma unroll
            for (int i = 0; i < 8; i++) a[i] = As[kk][row0 + i];
#pragma unroll
            for (int j = 0; j < 8; j++) b[j] = Bs[kk][col0 + j];
#pragma unroll
            for (int i = 0; i < 8; i++)
#pragma unroll
                for (int j = 0; j < 8; j++) acc[i][j] += a[i] * b[j];
        }
        __syncthreads();
    }
    // transposed write: mel[b, n, t]; each (thread, j) writes 8 consecutive t
    const int b     = m0 / T_;
    const int tbase = (m0 % T_) + row0;
#pragma unroll
    for (int j = 0; j < 8; j++) {
        const int nn = col0 + j;
        float* dst = mel + ((long)(b * MELS_ + nn)) * T_ + tbase;
        const float bv = bias[nn];
#pragma unroll
        for (int i = 0; i < 8; i++) dst[i] = acc[i][j] + bv;
    }
}

// ---------------------------------------------------------------------------
extern "C" void kernel_launch(void* const* d_in, const int* in_sizes, int n_in,
                              void* d_out, int out_size)
{
    const int* src = (const int*)d_in[0];
    const int* dur = (const int*)d_in[1];
    int p = 2;
    if (p < n_in && in_sizes[2] <= 4) p = 3;  // skip scalar T if materialized
    const float* emb   = (const float*)d_in[p + 0];
    const float* pos   = (const float*)d_in[p + 1];
    const float* W_enc = (const float*)d_in[p + 2];
    const float* b_enc = (const float*)d_in[p + 3];
    const float* W_dur = (const float*)d_in[p + 4];
    const float* b_dur = (const float*)d_in[p + 5];
    const float* W_dec = (const float*)d_in[p + 6];
    const float* b_dec = (const float*)d_in[p + 7];
    const float* W_gen = (const float*)d_in[p + 8];
    const float* b_gen = (const float*)d_in[p + 9];

    float* mel  = (float*)d_out;                       // [B, MELS, T]
    float* durp = (float*)d_out + (long)B_ * MELS_ * T_; // [B, L]

    tok_kernel<<<B_, 256>>>(dur);
    enc_gemm<<<dim3(D_ / 128, M_ENC / 128), 256>>>(src, emb, pos, W_enc, b_enc);
    dur_kernel<<<M_ENC / 8, dim3(32, 8)>>>(W_dur, b_dur, durp);
    dec_gemm<<<dim3(D_ / 128, M_DEC / 128), 256>>>(W_dec, b_dec);
    gen_gemm<<<dim3(1, M_DEC / 128), 160>>>(W_gen, b_gen, mel);
}

// round 2
// speedup vs baseline: 3.6038x; 3.6038x over previous
#include <cuda_runtime.h>
#include <cstdint>

#define B_    16
#define L_    256
#define D_    512
#define MELS_ 80
#define T_    3072
#define M_ENC (B_ * L_)   // 4096
#define M_DEC (B_ * T_)   // 49152

// Scratch (__device__ globals; no allocation allowed)
__device__ float g_x  [M_ENC * D_];   // tf32(emb[src]+pos)
__device__ float g_enc[M_ENC * D_];   // tf32(relu(enc))
__device__ float g_dec[M_DEC * D_];   // tf32(relu(dec))
__device__ int   g_aidx[M_DEC];       // gather row index, -1 = zero row
__device__ float g_wenc[D_ * D_];     // tf32 weights
__device__ float g_wdec[D_ * D_];
__device__ float g_wgen[D_ * MELS_];

__device__ __forceinline__ float cvt_tf32(float x) {
    uint32_t u; asm("cvt.rna.tf32.f32 %0, %1;" : "=r"(u) : "f"(x));
    return __uint_as_float(u);
}

__device__ __forceinline__ void cpa16(uint32_t dst, const void* src, int srcsize) {
    asm volatile("cp.async.cg.shared.global [%0], [%1], 16, %2;"
                 :: "r"(dst), "l"(src), "r"(srcsize));
}

__device__ __forceinline__ void mma_tf32(float* d, const float* a, const float* b) {
    asm volatile(
        "mma.sync.aligned.m16n8k8.row.col.f32.tf32.tf32.f32 "
        "{%0,%1,%2,%3},{%4,%5,%6,%7},{%8,%9},{%0,%1,%2,%3};"
        : "+f"(d[0]), "+f"(d[1]), "+f"(d[2]), "+f"(d[3])
        : "r"(__float_as_uint(a[0])), "r"(__float_as_uint(a[1])),
          "r"(__float_as_uint(a[2])), "r"(__float_as_uint(a[3])),
          "r"(__float_as_uint(b[0])), "r"(__float_as_uint(b[1])));
}

// ---------------------------------------------------------------------------
// prep: fp32 -> tf32 weight copies
// ---------------------------------------------------------------------------
__global__ void cvtw_kernel(const float* __restrict__ src, float* __restrict__ dst) {
    const long i = ((long)blockIdx.x * 256 + threadIdx.x) * 4;
    float4 v = *(const float4*)(src + i);
    float4 o = make_float4(cvt_tf32(v.x), cvt_tf32(v.y), cvt_tf32(v.z), cvt_tf32(v.w));
    *(float4*)(dst + i) = o;
}

// prep: g_x[m][d] = tf32(emb[src[m]][d] + pos[m % L][d])
__global__ void prep_x_kernel(const int* __restrict__ src, const float* __restrict__ emb,
                              const float* __restrict__ pos) {
    const long idx = (long)blockIdx.x * 256 + threadIdx.x;   // float4 index
    const int  m   = (int)(idx >> 7);
    const int  d4  = (int)(idx & 127) * 4;
    float4 e = *(const float4*)(emb + (long)src[m] * D_ + d4);
    float4 p = *(const float4*)(pos + (long)(m & (L_ - 1)) * D_ + d4);
    float4 o = make_float4(cvt_tf32(e.x + p.x), cvt_tf32(e.y + p.y),
                           cvt_tf32(e.z + p.z), cvt_tf32(e.w + p.w));
    *(float4*)(g_x + idx * 4) = o;
}

// ---------------------------------------------------------------------------
// tok: per-batch inclusive scan + per-frame searchsorted
// ---------------------------------------------------------------------------
__global__ void tok_kernel(const int* __restrict__ dur) {
    __shared__ int csum[L_];
    const int b = blockIdx.x, tid = threadIdx.x;
    csum[tid] = dur[b * L_ + tid];
    __syncthreads();
    for (int off = 1; off < L_; off <<= 1) {
        int x = (tid >= off) ? csum[tid - off] : 0;
        __syncthreads();
        csum[tid] += x;
        __syncthreads();
    }
    for (int t = tid; t < T_; t += blockDim.x) {
        int lo = 0, hi = L_;
        while (lo < hi) {
            int mid = (lo + hi) >> 1;
            if (csum[mid] > t) hi = mid; else lo = mid + 1;
        }
        g_aidx[b * T_ + t] = (lo < L_) ? (b * L_ + lo) : -1;
    }
}

// ---------------------------------------------------------------------------
// gemm512: out = tf32(relu(A_gathered @ Bt + bias)),  K = N = 512
//   A rows: aidx ? g_enc[aidx[m]] (zero if -1) : A[m]
//   mma.sync m16n8k8 tf32, 128x128x32 tiles, cp.async double buffer
// ---------------------------------------------------------------------------
#define AST 36          // A smem row stride (floats), 36 % 32 = 4
#define BST 136         // B smem row stride, 136 % 32 = 8
#define A_TILE (128 * AST)
#define B_TILE (32 * BST)
#define STAGE  (A_TILE + B_TILE)

__global__ void __launch_bounds__(256, 2) gemm512(
    const float* __restrict__ A, const int* __restrict__ aidx,
    const float* __restrict__ Bt, const float* __restrict__ bias,
    float* __restrict__ out)
{
    extern __shared__ float smem[];
    const int tid  = threadIdx.x;
    const int lane = tid & 31;
    const int m0   = blockIdx.y * 128;
    const int n0   = blockIdx.x * 128;

    // A-tile load mapping: 2 threads per row, 64B each
    const int lrow = tid >> 1;
    const int aseg = (tid & 1) * 16;
    const float* arow;
    int asz = 16;
    if (aidx) {
        int ai = aidx[m0 + lrow];
        if (ai < 0) { asz = 0; arow = A; }
        else arow = A + (long)ai * D_;
    } else {
        arow = A + (long)(m0 + lrow) * D_;
    }
    arow += aseg;

    const uint32_t sbase = (uint32_t)__cvta_generic_to_shared(smem);

    // warp tiling: 2 (m) x 4 (n) warps; warp tile 64m x 32n
    const int warp  = tid >> 5;
    const int mbase = (warp & 1) * 64;
    const int nbase = (warp >> 1) * 32;
    const int g = lane >> 2, t = lane & 3;

    float acc[4][4][4] = {};

#define ISSUE(it, buf) do {                                                   \
        uint32_t ab = sbase + (buf) * (STAGE * 4);                            \
        uint32_t bb = ab + A_TILE * 4;                                        \
        int k0 = (it) * 32;                                                   \
        uint32_t ad = ab + (lrow * AST + aseg) * 4;                           \
        const float* as_ = arow + k0;                                         \
        _Pragma("unroll")                                                     \
        for (int i = 0; i < 4; i++) cpa16(ad + i * 16, as_ + i * 4, asz);     \
        _Pragma("unroll")                                                     \
        for (int i = 0; i < 4; i++) {                                         \
            int idx = tid + i * 256;                                          \
            int kk = idx >> 5, n4 = (idx & 31) * 4;                           \
            cpa16(bb + (kk * BST + n4) * 4,                                   \
                  Bt + (long)(k0 + kk) * D_ + n0 + n4, 16);                   \
        }                                                                     \
        asm volatile("cp.async.commit_group;");                               \
    } while (0)

    ISSUE(0, 0);
#pragma unroll 1
    for (int it = 0; it < 16; ++it) {
        if (it + 1 < 16) {
            ISSUE(it + 1, (it + 1) & 1);
            asm volatile("cp.async.wait_group 1;");
        } else {
            asm volatile("cp.async.wait_group 0;");
        }
        __syncthreads();

        const float* As = smem + (it & 1) * STAGE;
        const float* Bs = As + A_TILE;
#pragma unroll
        for (int ks = 0; ks < 4; ks++) {
            const int k = ks * 8;
            float a[4][4], b[4][2];
#pragma unroll
            for (int mf = 0; mf < 4; mf++) {
                const int r = mbase + mf * 16 + g;
                a[mf][0] = As[r * AST + k + t];
                a[mf][1] = As[(r + 8) * AST + k + t];
                a[mf][2] = As[r * AST + k + t + 4];
                a[mf][3] = As[(r + 8) * AST + k + t + 4];
            }
#pragma unroll
            for (int nf = 0; nf < 4; nf++) {
                const int c = nbase + nf * 8 + g;
                b[nf][0] = Bs[(k + t) * BST + c];
                b[nf][1] = Bs[(k + t + 4) * BST + c];
            }
#pragma unroll
            for (int mf = 0; mf < 4; mf++)
#pragma unroll
                for (int nf = 0; nf < 4; nf++)
                    mma_tf32(acc[mf][nf], a[mf], b[nf]);
        }
        __syncthreads();
    }

    // epilogue: bias + relu + tf32 round, float2 stores
#pragma unroll
    for (int mf = 0; mf < 4; mf++) {
        const long r0 = m0 + mbase + mf * 16 + g;
#pragma unroll
        for (int nf = 0; nf < 4; nf++) {
            const int c = n0 + nbase + nf * 8 + t * 2;
            const float b0 = bias[c], b1 = bias[c + 1];
            float v0 = acc[mf][nf][0] + b0, v1 = acc[mf][nf][1] + b1;
            float v2 = acc[mf][nf][2] + b0, v3 = acc[mf][nf][3] + b1;
            float2 w0 = make_float2(cvt_tf32(v0 > 0.f ? v0 : 0.f),
                                    cvt_tf32(v1 > 0.f ? v1 : 0.f));
            float2 w1 = make_float2(cvt_tf32(v2 > 0.f ? v2 : 0.f),
                                    cvt_tf32(v3 > 0.f ? v3 : 0.f));
            *(float2*)(out + r0 * D_ + c)       = w0;
            *(float2*)(out + (r0 + 8) * D_ + c) = w1;
        }
    }
#undef ISSUE
}

// ---------------------------------------------------------------------------
// gen80: mel[b,n,t] = dec @ W_gen + b_gen (transposed store), N = 80
// ---------------------------------------------------------------------------
#define GBST 88         // 88 % 32 = 24 -> frag bank = 24t+g, bijective
#define GB_TILE (32 * GBST)
#define GSTAGE  (A_TILE + GB_TILE)

__global__ void __launch_bounds__(256, 2) gen80(
    const float* __restrict__ Bt, const float* __restrict__ bias,
    float* __restrict__ mel)
{
    extern __shared__ float smem[];
    const int tid  = threadIdx.x;
    const int lane = tid & 31;
    const int m0   = blockIdx.y * 128;

    const int lrow = tid >> 1;
    const int aseg = (tid & 1) * 16;
    const float* arow = g_dec + (long)(m0 + lrow) * D_ + aseg;

    const uint32_t sbase = (uint32_t)__cvta_generic_to_shared(smem);

    // 4 (m) x 2 (n) warps; warp tile 32m x 40n; 2 m-frags x 5 n-frags
    const int warp  = tid >> 5;
    const int mbase = (warp & 3) * 32;
    const int nbase = (warp >> 2) * 40;
    const int g = lane >> 2, t = lane & 3;

    float acc[2][5][4] = {};

#define GISSUE(it, buf) do {                                                  \
        uint32_t ab = sbase + (buf) * (GSTAGE * 4);                           \
        uint32_t bb = ab + A_TILE * 4;                                        \
        int k0 = (it) * 32;                                                   \
        uint32_t ad = ab + (lrow * AST + aseg) * 4;                           \
        const float* as_ = arow + k0;                                         \
        _Pragma("unroll")                                                     \
        for (int i = 0; i < 4; i++) cpa16(ad + i * 16, as_ + i * 4, 16);      \
        _Pragma("unroll")                                                     \
        for (int i = 0; i < 3; i++) {                                         \
            int idx = tid + i * 256;                                          \
            if (idx < 640) {                                                  \
                int kk = idx / 20, n4 = (idx % 20) * 4;                       \
                cpa16(bb + (kk * GBST + n4) * 4,                              \
                      Bt + (long)(k0 + kk) * MELS_ + n4, 16);                 \
            }                                                                 \
        }                                                                     \
        asm volatile("cp.async.commit_group;");                               \
    } while (0)

    GISSUE(0, 0);
#pragma unroll 1
    for (int it = 0; it < 16; ++it) {
        if (it + 1 < 16) {
            GISSUE(it + 1, (it + 1) & 1);
            asm volatile("cp.async.wait_group 1;");
        } else {
            asm volatile("cp.async.wait_group 0;");
        }
        __syncthreads();

        const float* As = smem + (it & 1) * GSTAGE;
        const float* Bs = As + A_TILE;
#pragma unroll
        for (int ks = 0; ks < 4; ks++) {
            const int k = ks * 8;
            float a[2][4], b[5][2];
#pragma unroll
            for (int mf = 0; mf < 2; mf++) {
                const int r = mbase + mf * 16 + g;
                a[mf][0] = As[r * AST + k + t];
                a[mf][1] = As[(r + 8) * AST + k + t];
                a[mf][2] = As[r * AST + k + t + 4];
                a[mf][3] = As[(r + 8) * AST + k + t + 4];
            }
#pragma unroll
            for (int nf = 0; nf < 5; nf++) {
                const int c = nbase + nf * 8 + g;
                b[nf][0] = Bs[(k + t) * GBST + c];
                b[nf][1] = Bs[(k + t + 4) * GBST + c];
            }
#pragma unroll
            for (int mf = 0; mf < 2; mf++)
#pragma unroll
                for (int nf = 0; nf < 5; nf++)
                    mma_tf32(acc[mf][nf], a[mf], b[nf]);
        }
        __syncthreads();
    }

    // transposed epilogue: mel[b, n, t]
#pragma unroll
    for (int mf = 0; mf < 2; mf++) {
        const int rg = m0 + mbase + mf * 16 + g;   // global decoder row
        const int b  = rg / T_;
        const int tt = rg % T_;
#pragma unroll
        for (int nf = 0; nf < 5; nf++) {
            const int n = nbase + nf * 8 + t * 2;
            const float b0 = bias[n], b1 = bias[n + 1];
            float* p0 = mel + ((long)b * MELS_ + n) * T_;
            float* p1 = p0 + T_;
            p0[tt]     = acc[mf][nf][0] + b0;
            p1[tt]     = acc[mf][nf][1] + b1;
            p0[tt + 8] = acc[mf][nf][2] + b0;
            p1[tt + 8] = acc[mf][nf][3] + b1;
        }
    }
#undef GISSUE
}

// ---------------------------------------------------------------------------
// duration head
// ---------------------------------------------------------------------------
__global__ void dur_kernel(const float* __restrict__ Wd, const float* __restrict__ bd,
                           float* __restrict__ out)
{
    const int m    = blockIdx.x * 8 + threadIdx.y;
    const int lane = threadIdx.x;
    float s = 0.f;
    for (int k = lane; k < D_; k += 32) s += g_enc[(long)m * D_ + k] * Wd[k];
#pragma unroll
    for (int o = 16; o; o >>= 1) s += __shfl_xor_sync(0xffffffffu, s, o);
    if (lane == 0) out[m] = s + bd[0];
}

// ---------------------------------------------------------------------------
extern "C" void kernel_launch(void* const* d_in, const int* in_sizes, int n_in,
                              void* d_out, int out_size)
{
    const int* src = (const int*)d_in[0];
    const int* dur = (const int*)d_in[1];
    int p = 2;
    if (p < n_in && in_sizes[2] <= 4) p = 3;  // skip scalar T if materialized
    const float* emb   = (const float*)d_in[p + 0];
    const float* pos   = (const float*)d_in[p + 1];
    const float* W_enc = (const float*)d_in[p + 2];
    const float* b_enc = (const float*)d_in[p + 3];
    const float* W_dur = (const float*)d_in[p + 4];
    const float* b_dur = (const float*)d_in[p + 5];
    const float* W_dec = (const float*)d_in[p + 6];
    const float* b_dec = (const float*)d_in[p + 7];
    const float* W_gen = (const float*)d_in[p + 8];
    const float* b_gen = (const float*)d_in[p + 9];

    float* mel  = (float*)d_out;                         // [B, MELS, T]
    float* durp = (float*)d_out + (long)B_ * MELS_ * T_; // [B, L]

    static bool attr_done = false;
    if (!attr_done) {
        cudaFuncSetAttribute(gemm512, cudaFuncAttributeMaxDynamicSharedMemorySize,
                             2 * STAGE * 4);
        cudaFuncSetAttribute(gen80, cudaFuncAttributeMaxDynamicSharedMemorySize,
                             2 * GSTAGE * 4);
        attr_done = true;
    }

    float *d_wenc, *d_wdec, *d_wgen, *d_x, *d_enc, *d_decb;
    int* d_aidx;
    cudaGetSymbolAddress((void**)&d_wenc, g_wenc);
    cudaGetSymbolAddress((void**)&d_wdec, g_wdec);
    cudaGetSymbolAddress((void**)&d_wgen, g_wgen);
    cudaGetSymbolAddress((void**)&d_x,    g_x);
    cudaGetSymbolAddress((void**)&d_enc,  g_enc);
    cudaGetSymbolAddress((void**)&d_decb, g_dec);
    cudaGetSymbolAddress((void**)&d_aidx, g_aidx);

    cvtw_kernel<<<D_ * D_ / 1024, 256>>>(W_enc, d_wenc);
    cvtw_kernel<<<D_ * D_ / 1024, 256>>>(W_dec, d_wdec);
    cvtw_kernel<<<D_ * MELS_ / 1024, 256>>>(W_gen, d_wgen);
    prep_x_kernel<<<M_ENC * (D_ / 4) / 256, 256>>>(src, emb, pos);
    tok_kernel<<<B_, 256>>>(dur);

    gemm512<<<dim3(D_ / 128, M_ENC / 128), 256, 2 * STAGE * 4>>>(
        d_x, nullptr, d_wenc, b_enc, d_enc);
    dur_kernel<<<M_ENC / 8, dim3(32, 8)>>>(W_dur, b_dur, durp);
    gemm512<<<dim3(D_ / 128, M_DEC / 128), 256, 2 * STAGE * 4>>>(
        d_enc, d_aidx, d_wdec, b_dec, d_decb);
    gen80<<<dim3(1, M_DEC / 128), 256, 2 * GSTAGE * 4>>>(d_wgen, b_gen, mel);
}

// round 4
// speedup vs baseline: 4.7879x; 1.3286x over previous
#include <cuda_runtime.h>
#include <cuda_fp16.h>
#include <cstdint>

#define B_    16
#define L_    256
#define D_    512
#define MELS_ 80
#define T_    3072
#define M_ENC (B_ * L_)   // 4096
#define M_DEC (B_ * T_)   // 49152

// Scratch (__device__ globals; no allocation allowed)
__device__ __half g_x   [M_ENC * D_];   // fp16(emb[src]+pos)
__device__ __half g_enc [M_ENC * D_];   // fp16(relu(enc))
__device__ __half g_dec [M_DEC * D_];   // fp16(relu(dec))
__device__ int    g_aidx[M_DEC];        // gather row index, -1 = zero row
__device__ __half g_wencT[D_ * D_];     // fp16 W^T  [N][K]
__device__ __half g_wdecT[D_ * D_];
__device__ __half g_wgenT[MELS_ * D_];

// ---------------------------------------------------------------------------
__device__ __forceinline__ uint32_t smem_u32(const void* p) {
    return (uint32_t)__cvta_generic_to_shared(p);
}
__device__ __forceinline__ void cpa16(uint32_t dst, const void* src, int srcsize) {
    asm volatile("cp.async.cg.shared.global [%0], [%1], 16, %2;"
                 :: "r"(dst), "l"(src), "r"(srcsize));
}
__device__ __forceinline__ uint32_t sw(uint32_t o) { return o ^ ((o >> 3) & 0x70); }

__device__ __forceinline__ void ldm4(uint32_t* r, uint32_t addr) {
    asm volatile("ldmatrix.sync.aligned.m8n8.x4.shared.b16 {%0,%1,%2,%3}, [%4];"
                 : "=r"(r[0]), "=r"(r[1]), "=r"(r[2]), "=r"(r[3]) : "r"(addr));
}
__device__ __forceinline__ void ldm2(uint32_t* r, uint32_t addr) {
    asm volatile("ldmatrix.sync.aligned.m8n8.x2.shared.b16 {%0,%1}, [%2];"
                 : "=r"(r[0]), "=r"(r[1]) : "r"(addr));
}
__device__ __forceinline__ void mma_f16(float* d, const uint32_t* a, const uint32_t* b) {
    asm volatile(
        "mma.sync.aligned.m16n8k16.row.col.f32.f16.f16.f32 "
        "{%0,%1,%2,%3},{%4,%5,%6,%7},{%8,%9},{%0,%1,%2,%3};"
        : "+f"(d[0]), "+f"(d[1]), "+f"(d[2]), "+f"(d[3])
        : "r"(a[0]), "r"(a[1]), "r"(a[2]), "r"(a[3]), "r"(b[0]), "r"(b[1]));
}

// ---------------------------------------------------------------------------
// prep: transpose + fp16 round:  dst[c][r] = fp16(src[r][c])
// ---------------------------------------------------------------------------
__global__ void transpose_f16(const float* __restrict__ src, __half* __restrict__ dst,
                              int R, int C) {
    __shared__ float tile[32][33];
    const int c0 = blockIdx.x * 32, r0 = blockIdx.y * 32;
#pragma unroll
    for (int i = 0; i < 4; i++) {
        int r = r0 + threadIdx.y + i * 8, c = c0 + threadIdx.x;
        if (r < R && c < C) tile[threadIdx.y + i * 8][threadIdx.x] = src[r * C + c];
    }
    __syncthreads();
#pragma unroll
    for (int i = 0; i < 4; i++) {
        int c = c0 + threadIdx.y + i * 8, r = r0 + threadIdx.x;
        if (c < C && r < R)
            dst[(long)c * R + r] = __float2half_rn(tile[threadIdx.x][threadIdx.y + i * 8]);
    }
}

// prep: g_x[m][d] = fp16(emb[src[m]][d] + pos[m % L][d])
__global__ void prep_x_kernel(const int* __restrict__ src, const float* __restrict__ emb,
                              const float* __restrict__ pos) {
    const long idx = (long)blockIdx.x * 256 + threadIdx.x;   // float4 index
    const int  m   = (int)(idx >> 7);
    const int  d4  = (int)(idx & 127) * 4;
    float4 e = *(const float4*)(emb + (long)src[m] * D_ + d4);
    float4 p = *(const float4*)(pos + (long)(m & (L_ - 1)) * D_ + d4);
    __half2 h0 = __floats2half2_rn(e.x + p.x, e.y + p.y);
    __half2 h1 = __floats2half2_rn(e.z + p.z, e.w + p.w);
    uint2 u = make_uint2(*(uint32_t*)&h0, *(uint32_t*)&h1);
    *(uint2*)(g_x + idx * 4) = u;
}

// ---------------------------------------------------------------------------
// tok: per-batch inclusive scan + per-frame searchsorted
// ---------------------------------------------------------------------------
__global__ void tok_kernel(const int* __restrict__ dur) {
    __shared__ int csum[L_];
    const int b = blockIdx.x, tid = threadIdx.x;
    csum[tid] = dur[b * L_ + tid];
    __syncthreads();
    for (int off = 1; off < L_; off <<= 1) {
        int x = (tid >= off) ? csum[tid - off] : 0;
        __syncthreads();
        csum[tid] += x;
        __syncthreads();
    }
    for (int t = tid; t < T_; t += blockDim.x) {
        int lo = 0, hi = L_;
        while (lo < hi) {
            int mid = (lo + hi) >> 1;
            if (csum[mid] > t) hi = mid; else lo = mid + 1;
        }
        g_aidx[b * T_ + t] = (lo < L_) ? (b * L_ + lo) : -1;
    }
}

// ---------------------------------------------------------------------------
// hgemm512: out = fp16(relu(A_gathered @ Bt^T + bias)),  K = N = 512, fp16 in
//   128x128 CTA tile, BK = 64 halves (128 B), double-buffered cp.async
//   8 warps (2m x 4n), ldmatrix fragments, mma.m16n8k16
// ---------------------------------------------------------------------------
#define H_ATILE 16384          // 128 rows * 128 B
#define H_STAGE (2 * H_ATILE)  // A + B
#define SMEM512 (2 * H_STAGE + 1024)

__global__ void __launch_bounds__(256, 2) hgemm512(
    const __half* __restrict__ A, const int* __restrict__ aidx,
    const __half* __restrict__ Bt, const float* __restrict__ bias,
    __half* __restrict__ out)
{
    extern __shared__ char dsm[];
    const int tid  = threadIdx.x;
    const int warp = tid >> 5, lane = tid & 31;
    const int m0   = blockIdx.y * 128, n0 = blockIdx.x * 128;

    const uint32_t base = (smem_u32(dsm) + 1023) & ~1023u;
    const uint32_t Aoff[2] = { base, base + H_STAGE };
    const uint32_t Boff[2] = { base + H_ATILE, base + H_STAGE + H_ATILE };

    // loads: 4 A rows + 4 B rows per thread, 16B each per stage
    const int r0  = tid >> 3;
    const int seg = (tid & 7) * 16;
    const char* ap[4]; int asz[4];
    const char* bp[4];
    uint32_t dst[4];
#pragma unroll
    for (int i = 0; i < 4; i++) {
        const int r = r0 + i * 32;
        if (aidx) {
            int ai = aidx[m0 + r];
            if (ai < 0) { ap[i] = (const char*)A; asz[i] = 0; }
            else        { ap[i] = (const char*)A + (long)ai * D_ * 2; asz[i] = 16; }
        } else {
            ap[i] = (const char*)A + (long)(m0 + r) * D_ * 2; asz[i] = 16;
        }
        bp[i]  = (const char*)Bt + (long)(n0 + r) * D_ * 2;
        dst[i] = sw((uint32_t)(r * 128 + seg));
    }

#define HISSUE(c, s) do {                                                     \
        const int kb = (c) * 128;                                             \
        _Pragma("unroll")                                                     \
        for (int i = 0; i < 4; i++) cpa16(Aoff[s] + dst[i], ap[i] + kb + seg, asz[i]); \
        _Pragma("unroll")                                                     \
        for (int i = 0; i < 4; i++) cpa16(Boff[s] + dst[i], bp[i] + kb + seg, 16);     \
        asm volatile("cp.async.commit_group;");                               \
    } while (0)

    // fragment addressing components
    const int mbase = (warp & 1) * 64;
    const int nbase = (warp >> 1) * 32;
    const int li  = lane & 7, grp = lane >> 3;
    const int ar  = (grp & 1) * 8 + li,  ak = (grp >> 1) * 16;   // A ldmatrix
    const int br  = (grp >> 1) * 8 + li, bk = (grp & 1) * 16;    // B ldmatrix
    const int g = lane >> 2, t = lane & 3;

    float acc[4][4][4] = {};

    HISSUE(0, 0);
#pragma unroll 1
    for (int c = 0; c < 8; c++) {
        if (c < 7) {
            HISSUE(c + 1, (c + 1) & 1);
            asm volatile("cp.async.wait_group 1;");
        } else {
            asm volatile("cp.async.wait_group 0;");
        }
        __syncthreads();
        const uint32_t Ab = Aoff[c & 1], Bb = Boff[c & 1];
#pragma unroll
        for (int kk = 0; kk < 4; kk++) {
            const int kb2 = kk * 32;
            uint32_t a[4][4], b[4][2];
#pragma unroll
            for (int mf = 0; mf < 4; mf++) {
                uint32_t o = (uint32_t)((mbase + mf * 16 + ar) * 128 + kb2 + ak);
                ldm4(a[mf], Ab + sw(o));
            }
#pragma unroll
            for (int nfp = 0; nfp < 2; nfp++) {
                uint32_t o = (uint32_t)((nbase + nfp * 16 + br) * 128 + kb2 + bk);
                uint32_t r[4]; ldm4(r, Bb + sw(o));
                b[nfp * 2][0] = r[0]; b[nfp * 2][1] = r[1];
                b[nfp * 2 + 1][0] = r[2]; b[nfp * 2 + 1][1] = r[3];
            }
#pragma unroll
            for (int mf = 0; mf < 4; mf++)
#pragma unroll
                for (int nf = 0; nf < 4; nf++)
                    mma_f16(acc[mf][nf], a[mf], b[nf]);
        }
        __syncthreads();
    }

    // epilogue: bias + relu + fp16 round, half2 stores
#pragma unroll
    for (int mf = 0; mf < 4; mf++) {
        const long r0g = m0 + mbase + mf * 16 + g;
#pragma unroll
        for (int nf = 0; nf < 4; nf++) {
            const int c = n0 + nbase + nf * 8 + t * 2;
            const float b0 = bias[c], b1 = bias[c + 1];
            float v0 = acc[mf][nf][0] + b0, v1 = acc[mf][nf][1] + b1;
            float v2 = acc[mf][nf][2] + b0, v3 = acc[mf][nf][3] + b1;
            __half2 h0 = __floats2half2_rn(v0 > 0.f ? v0 : 0.f, v1 > 0.f ? v1 : 0.f);
            __half2 h1 = __floats2half2_rn(v2 > 0.f ? v2 : 0.f, v3 > 0.f ? v3 : 0.f);
            *(__half2*)(out + r0g * D_ + c)       = h0;
            *(__half2*)(out + (r0g + 8) * D_ + c) = h1;
        }
    }
#undef HISSUE
}

// ---------------------------------------------------------------------------
// hgen80: mel[b,n,t] = dec @ W_gen^T + b_gen (transposed fp32 store), N = 80
// ---------------------------------------------------------------------------
#define HG_BTILE 10240         // 80 rows * 128 B
#define HG_STAGE (H_ATILE + HG_BTILE)
#define SMEM80 (2 * HG_STAGE + 1024)

__global__ void __launch_bounds__(256, 2) hgen80(
    const float* __restrict__ bias, float* __restrict__ mel)
{
    extern __shared__ char dsm[];
    const int tid  = threadIdx.x;
    const int warp = tid >> 5, lane = tid & 31;
    const int m0   = blockIdx.y * 128;

    const uint32_t base = (smem_u32(dsm) + 1023) & ~1023u;
    const uint32_t Aoff[2] = { base, base + HG_STAGE };
    const uint32_t Boff[2] = { base + H_ATILE, base + HG_STAGE + H_ATILE };

    const int r0  = tid >> 3;
    const int seg = (tid & 7) * 16;
    const char* ap[4]; uint32_t adst[4];
    const char* bp[3]; uint32_t bdst[3]; int bok[3];
#pragma unroll
    for (int i = 0; i < 4; i++) {
        const int r = r0 + i * 32;
        ap[i]   = (const char*)g_dec + (long)(m0 + r) * D_ * 2;
        adst[i] = sw((uint32_t)(r * 128 + seg));
    }
#pragma unroll
    for (int i = 0; i < 3; i++) {
        const int r = r0 + i * 32;
        bok[i]  = (r < MELS_);
        bp[i]   = (const char*)g_wgenT + (long)(bok[i] ? r : 0) * D_ * 2;
        bdst[i] = sw((uint32_t)(r * 128 + seg));
    }

#define GISSUE(c, s) do {                                                     \
        const int kb = (c) * 128;                                             \
        _Pragma("unroll")                                                     \
        for (int i = 0; i < 4; i++) cpa16(Aoff[s] + adst[i], ap[i] + kb + seg, 16); \
        _Pragma("unroll")                                                     \
        for (int i = 0; i < 3; i++)                                           \
            if (bok[i]) cpa16(Boff[s] + bdst[i], bp[i] + kb + seg, 16);       \
        asm volatile("cp.async.commit_group;");                               \
    } while (0)

    const int mbase = (warp & 3) * 32;
    const int nbase = (warp >> 2) * 40;
    const int li  = lane & 7, grp = lane >> 3;
    const int ar  = (grp & 1) * 8 + li,  ak = (grp >> 1) * 16;
    const int br  = (grp >> 1) * 8 + li, bk = (grp & 1) * 16;
    const int g = lane >> 2, t = lane & 3;

    float acc[2][5][4] = {};

    GISSUE(0, 0);
#pragma unroll 1
    for (int c = 0; c < 8; c++) {
        if (c < 7) {
            GISSUE(c + 1, (c + 1) & 1);
            asm volatile("cp.async.wait_group 1;");
        } else {
            asm volatile("cp.async.wait_group 0;");
        }
        __syncthreads();
        const uint32_t Ab = Aoff[c & 1], Bb = Boff[c & 1];
#pragma unroll
        for (int kk = 0; kk < 4; kk++) {
            const int kb2 = kk * 32;
            uint32_t a[2][4], b[5][2];
#pragma unroll
            for (int mf = 0; mf < 2; mf++) {
                uint32_t o = (uint32_t)((mbase + mf * 16 + ar) * 128 + kb2 + ak);
                ldm4(a[mf], Ab + sw(o));
            }
#pragma unroll
            for (int nfp = 0; nfp < 2; nfp++) {
                uint32_t o = (uint32_t)((nbase + nfp * 16 + br) * 128 + kb2 + bk);
                uint32_t r[4]; ldm4(r, Bb + sw(o));
                b[nfp * 2][0] = r[0]; b[nfp * 2][1] = r[1];
                b[nfp * 2 + 1][0] = r[2]; b[nfp * 2 + 1][1] = r[3];
            }
            {   // last n-frag (rows nbase+32..39) via x2
                uint32_t o = (uint32_t)((nbase + 32 + li) * 128 + kb2 + (grp & 1) * 16);
                ldm2(b[4], Bb + sw(o));
            }
#pragma unroll
            for (int mf = 0; mf < 2; mf++)
#pragma unroll
                for (int nf = 0; nf < 5; nf++)
                    mma_f16(acc[mf][nf], a[mf], b[nf]);
        }
        __syncthreads();
    }

    // transposed epilogue: mel[b, n, t]
#pragma unroll
    for (int mf = 0; mf < 2; mf++) {
        const int rg = m0 + mbase + mf * 16 + g;
        const int b  = rg / T_;
        const int tt = rg - b * T_;
#pragma unroll
        for (int nf = 0; nf < 5; nf++) {
            const int n = nbase + nf * 8 + t * 2;
            const float b0 = bias[n], b1 = bias[n + 1];
            float* p0 = mel + ((long)b * MELS_ + n) * T_;
            float* p1 = p0 + T_;
            p0[tt]     = acc[mf][nf][0] + b0;
            p1[tt]     = acc[mf][nf][1] + b1;
            p0[tt + 8] = acc[mf][nf][2] + b0;
            p1[tt + 8] = acc[mf][nf][3] + b1;
        }
    }
#undef GISSUE
}

// ---------------------------------------------------------------------------
// duration head (reads fp16 enc)
// ---------------------------------------------------------------------------
__global__ void dur_kernel(const float* __restrict__ Wd, const float* __restrict__ bd,
                           float* __restrict__ out)
{
    const int m    = blockIdx.x * 8 + threadIdx.y;
    const int lane = threadIdx.x;
    float s = 0.f;
    for (int k = lane; k < D_; k += 32)
        s += __half2float(g_enc[(long)m * D_ + k]) * Wd[k];
#pragma unroll
    for (int o = 16; o; o >>= 1) s += __shfl_xor_sync(0xffffffffu, s, o);
    if (lane == 0) out[m] = s + bd[0];
}

// ---------------------------------------------------------------------------
extern "C" void kernel_launch(void* const* d_in, const int* in_sizes, int n_in,
                              void* d_out, int out_size)
{
    const int* src = (const int*)d_in[0];
    const int* dur = (const int*)d_in[1];
    int p = 2;
    if (p < n_in && in_sizes[2] <= 4) p = 3;  // skip scalar T if materialized
    const float* emb   = (const float*)d_in[p + 0];
    const float* pos   = (const float*)d_in[p + 1];
    const float* W_enc = (const float*)d_in[p + 2];
    const float* b_enc = (const float*)d_in[p + 3];
    const float* W_dur = (const float*)d_in[p + 4];
    const float* b_dur = (const float*)d_in[p + 5];
    const float* W_dec = (const float*)d_in[p + 6];
    const float* b_dec = (const float*)d_in[p + 7];
    const float* W_gen = (const float*)d_in[p + 8];
    const float* b_gen = (const float*)d_in[p + 9];

    float* mel  = (float*)d_out;                         // [B, MELS, T]
    float* durp = (float*)d_out + (long)B_ * MELS_ * T_; // [B, L]

    static bool attr_done = false;
    if (!attr_done) {
        cudaFuncSetAttribute(hgemm512, cudaFuncAttributeMaxDynamicSharedMemorySize, SMEM512);
        cudaFuncSetAttribute(hgen80,   cudaFuncAttributeMaxDynamicSharedMemorySize, SMEM80);
        attr_done = true;
    }

    __half *d_wencT, *d_wdecT, *d_wgenT, *d_x, *d_enc, *d_decb;
    int* d_aidx;
    cudaGetSymbolAddress((void**)&d_wencT, g_wencT);
    cudaGetSymbolAddress((void**)&d_wdecT, g_wdecT);
    cudaGetSymbolAddress((void**)&d_wgenT, g_wgenT);
    cudaGetSymbolAddress((void**)&d_x,     g_x);
    cudaGetSymbolAddress((void**)&d_enc,   g_enc);
    cudaGetSymbolAddress((void**)&d_decb,  g_dec);
    cudaGetSymbolAddress((void**)&d_aidx,  g_aidx);

    transpose_f16<<<dim3(16, 16), dim3(32, 8)>>>(W_enc, d_wencT, D_, D_);
    transpose_f16<<<dim3(16, 16), dim3(32, 8)>>>(W_dec, d_wdecT, D_, D_);
    transpose_f16<<<dim3(3, 16),  dim3(32, 8)>>>(W_gen, d_wgenT, D_, MELS_);
    prep_x_kernel<<<M_ENC * (D_ / 4) / 256, 256>>>(src, emb, pos);
    tok_kernel<<<B_, 256>>>(dur);

    hgemm512<<<dim3(D_ / 128, M_ENC / 128), 256, SMEM512>>>(
        d_x, nullptr, d_wencT, b_enc, d_enc);
    dur_kernel<<<M_ENC / 8, dim3(32, 8)>>>(W_dur, b_dur, durp);
    hgemm512<<<dim3(D_ / 128, M_DEC / 128), 256, SMEM512>>>(
        d_enc, d_aidx, d_wdecT, b_dec, d_decb);
    hgen80<<<dim3(1, M_DEC / 128), 256, SMEM80>>>(b_gen, mel);
}

// round 5
// speedup vs baseline: 10.1051x; 2.1105x over previous
#include <cuda_runtime.h>
#include <cuda_fp16.h>
#include <cstdint>

#define B_    16
#define L_    256
#define D_    512
#define MELS_ 80
#define T_    3072
#define M_ENC (B_ * L_)   // 4096
#define M_DEC (B_ * T_)   // 49152

// Scratch (__device__ globals; no allocation allowed)
__device__ __half g_x   [M_ENC * D_];   // fp16(emb[src]+pos)
__device__ __half g_enc [M_ENC * D_];   // fp16(relu(enc))
__device__ __half g_dec [M_DEC * D_];   // fp16(relu(dec))
__device__ int    g_aidx[M_DEC];        // gather row index, -1 = zero row
__device__ int    g_tot [B_];           // total valid frames per batch
__device__ float  g_cmel[MELS_];        // constant mel column for invalid frames
__device__ __half g_wencT[D_ * D_];     // fp16 W^T  [N][K]
__device__ __half g_wdecT[D_ * D_];
__device__ __half g_wgenT[MELS_ * D_];

// ---------------------------------------------------------------------------
__device__ __forceinline__ uint32_t smem_u32(const void* p) {
    return (uint32_t)__cvta_generic_to_shared(p);
}
__device__ __forceinline__ void cpa16(uint32_t dst, const void* src, int srcsize) {
    asm volatile("cp.async.cg.shared.global [%0], [%1], 16, %2;"
                 :: "r"(dst), "l"(src), "r"(srcsize));
}
__device__ __forceinline__ uint32_t sw(uint32_t o) { return o ^ ((o >> 3) & 0x70); }

__device__ __forceinline__ void ldm4(uint32_t* r, uint32_t addr) {
    asm volatile("ldmatrix.sync.aligned.m8n8.x4.shared.b16 {%0,%1,%2,%3}, [%4];"
                 : "=r"(r[0]), "=r"(r[1]), "=r"(r[2]), "=r"(r[3]) : "r"(addr));
}
__device__ __forceinline__ void ldm2(uint32_t* r, uint32_t addr) {
    asm volatile("ldmatrix.sync.aligned.m8n8.x2.shared.b16 {%0,%1}, [%2];"
                 : "=r"(r[0]), "=r"(r[1]) : "r"(addr));
}
__device__ __forceinline__ void mma_f16(float* d, const uint32_t* a, const uint32_t* b) {
    asm volatile(
        "mma.sync.aligned.m16n8k16.row.col.f32.f16.f16.f32 "
        "{%0,%1,%2,%3},{%4,%5,%6,%7},{%8,%9},{%0,%1,%2,%3};"
        : "+f"(d[0]), "+f"(d[1]), "+f"(d[2]), "+f"(d[3])
        : "r"(a[0]), "r"(a[1]), "r"(a[2]), "r"(a[3]), "r"(b[0]), "r"(b[1]));
}

// ---------------------------------------------------------------------------
// prep: transpose + fp16 round:  dst[c][r] = fp16(src[r][c])
// ---------------------------------------------------------------------------
__global__ void transpose_f16(const float* __restrict__ src, __half* __restrict__ dst,
                              int R, int C) {
    __shared__ float tile[32][33];
    const int c0 = blockIdx.x * 32, r0 = blockIdx.y * 32;
#pragma unroll
    for (int i = 0; i < 4; i++) {
        int r = r0 + threadIdx.y + i * 8, c = c0 + threadIdx.x;
        if (r < R && c < C) tile[threadIdx.y + i * 8][threadIdx.x] = src[r * C + c];
    }
    __syncthreads();
#pragma unroll
    for (int i = 0; i < 4; i++) {
        int c = c0 + threadIdx.y + i * 8, r = r0 + threadIdx.x;
        if (c < C && r < R)
            dst[(long)c * R + r] = __float2half_rn(tile[threadIdx.x][threadIdx.y + i * 8]);
    }
}

// prep: g_x[m][d] = fp16(emb[src[m]][d] + pos[m % L][d])
__global__ void prep_x_kernel(const int* __restrict__ src, const float* __restrict__ emb,
                              const float* __restrict__ pos) {
    const long idx = (long)blockIdx.x * 256 + threadIdx.x;   // float4 index
    const int  m   = (int)(idx >> 7);
    const int  d4  = (int)(idx & 127) * 4;
    float4 e = *(const float4*)(emb + (long)src[m] * D_ + d4);
    float4 p = *(const float4*)(pos + (long)(m & (L_ - 1)) * D_ + d4);
    __half2 h0 = __floats2half2_rn(e.x + p.x, e.y + p.y);
    __half2 h1 = __floats2half2_rn(e.z + p.z, e.w + p.w);
    uint2 u = make_uint2(*(uint32_t*)&h0, *(uint32_t*)&h1);
    *(uint2*)(g_x + idx * 4) = u;
}

// constant mel column for frames past total duration:
//   cmel[n] = relu(b_dec) . W_gen[:, n] + b_gen[n]   (fp32)
__global__ void cmel_kernel(const float* __restrict__ b_dec,
                            const float* __restrict__ W_gen,
                            const float* __restrict__ b_gen) {
    __shared__ float rd[D_];
    for (int k = threadIdx.x; k < D_; k += blockDim.x) {
        float v = b_dec[k]; rd[k] = v > 0.f ? v : 0.f;
    }
    __syncthreads();
    const int n = threadIdx.x;
    if (n < MELS_) {
        float s = b_gen[n];
        for (int k = 0; k < D_; k++) s += rd[k] * W_gen[k * MELS_ + n];
        g_cmel[n] = s;
    }
}

// ---------------------------------------------------------------------------
// tok: per-batch inclusive scan + per-frame searchsorted + total duration
// ---------------------------------------------------------------------------
__global__ void tok_kernel(const int* __restrict__ dur) {
    __shared__ int csum[L_];
    const int b = blockIdx.x, tid = threadIdx.x;
    csum[tid] = dur[b * L_ + tid];
    __syncthreads();
    for (int off = 1; off < L_; off <<= 1) {
        int x = (tid >= off) ? csum[tid - off] : 0;
        __syncthreads();
        csum[tid] += x;
        __syncthreads();
    }
    if (tid == 0) g_tot[b] = csum[L_ - 1];
    for (int t = tid; t < T_; t += blockDim.x) {
        int lo = 0, hi = L_;
        while (lo < hi) {
            int mid = (lo + hi) >> 1;
            if (csum[mid] > t) hi = mid; else lo = mid + 1;
        }
        g_aidx[b * T_ + t] = (lo < L_) ? (b * L_ + lo) : -1;
    }
}

// ---------------------------------------------------------------------------
// hgemm512: out = fp16(relu(A_gathered @ Bt^T + bias)),  K = N = 512, fp16 in
//   128x128 CTA tile, BK = 64 halves (128 B), double-buffered cp.async
//   8 warps (2m x 4n), ldmatrix fragments, mma.m16n8k16
//   tot != null (dec call): tiles entirely past the valid prefix exit early
// ---------------------------------------------------------------------------
#define H_ATILE 16384          // 128 rows * 128 B
#define H_STAGE (2 * H_ATILE)  // A + B
#define SMEM512 (2 * H_STAGE + 1024)

__global__ void __launch_bounds__(256, 2) hgemm512(
    const __half* __restrict__ A, const int* __restrict__ aidx,
    const int* __restrict__ tot,
    const __half* __restrict__ Bt, const float* __restrict__ bias,
    __half* __restrict__ out)
{
    extern __shared__ char dsm[];
    const int tid  = threadIdx.x;
    const int warp = tid >> 5, lane = tid & 31;
    const int m0   = blockIdx.y * 128, n0 = blockIdx.x * 128;

    if (tot && (m0 % T_) >= tot[m0 / T_]) return;   // fully-invalid frame tile

    const uint32_t base = (smem_u32(dsm) + 1023) & ~1023u;
    const uint32_t Aoff[2] = { base, base + H_STAGE };
    const uint32_t Boff[2] = { base + H_ATILE, base + H_STAGE + H_ATILE };

    // loads: 4 A rows + 4 B rows per thread, 16B each per stage
    const int r0  = tid >> 3;
    const int seg = (tid & 7) * 16;
    const char* ap[4]; int asz[4];
    const char* bp[4];
    uint32_t dst[4];
#pragma unroll
    for (int i = 0; i < 4; i++) {
        const int r = r0 + i * 32;
        if (aidx) {
            int ai = aidx[m0 + r];
            if (ai < 0) { ap[i] = (const char*)A; asz[i] = 0; }
            else        { ap[i] = (const char*)A + (long)ai * D_ * 2; asz[i] = 16; }
        } else {
            ap[i] = (const char*)A + (long)(m0 + r) * D_ * 2; asz[i] = 16;
        }
        bp[i]  = (const char*)Bt + (long)(n0 + r) * D_ * 2;
        dst[i] = sw((uint32_t)(r * 128 + seg));
    }

#define HISSUE(c, s) do {                                                     \
        const int kb = (c) * 128;                                             \
        _Pragma("unroll")                                                     \
        for (int i = 0; i < 4; i++) cpa16(Aoff[s] + dst[i], ap[i] + kb + seg, asz[i]); \
        _Pragma("unroll")                                                     \
        for (int i = 0; i < 4; i++) cpa16(Boff[s] + dst[i], bp[i] + kb + seg, 16);     \
        asm volatile("cp.async.commit_group;");                               \
    } while (0)

    // fragment addressing components
    const int mbase = (warp & 1) * 64;
    const int nbase = (warp >> 1) * 32;
    const int li  = lane & 7, grp = lane >> 3;
    const int ar  = (grp & 1) * 8 + li,  ak = (grp >> 1) * 16;   // A ldmatrix
    const int br  = (grp >> 1) * 8 + li, bk = (grp & 1) * 16;    // B ldmatrix
    const int g = lane >> 2, t = lane & 3;

    float acc[4][4][4] = {};

    HISSUE(0, 0);
#pragma unroll 1
    for (int c = 0; c < 8; c++) {
        if (c < 7) {
            HISSUE(c + 1, (c + 1) & 1);
            asm volatile("cp.async.wait_group 1;");
        } else {
            asm volatile("cp.async.wait_group 0;");
        }
        __syncthreads();
        const uint32_t Ab = Aoff[c & 1], Bb = Boff[c & 1];
#pragma unroll
        for (int kk = 0; kk < 4; kk++) {
            const int kb2 = kk * 32;
            uint32_t a[4][4], b[4][2];
#pragma unroll
            for (int mf = 0; mf < 4; mf++) {
                uint32_t o = (uint32_t)((mbase + mf * 16 + ar) * 128 + kb2 + ak);
                ldm4(a[mf], Ab + sw(o));
            }
#pragma unroll
            for (int nfp = 0; nfp < 2; nfp++) {
                uint32_t o = (uint32_t)((nbase + nfp * 16 + br) * 128 + kb2 + bk);
                uint32_t r[4]; ldm4(r, Bb + sw(o));
                b[nfp * 2][0] = r[0]; b[nfp * 2][1] = r[1];
                b[nfp * 2 + 1][0] = r[2]; b[nfp * 2 + 1][1] = r[3];
            }
#pragma unroll
            for (int mf = 0; mf < 4; mf++)
#pragma unroll
                for (int nf = 0; nf < 4; nf++)
                    mma_f16(acc[mf][nf], a[mf], b[nf]);
        }
        __syncthreads();
    }

    // epilogue: bias + relu + fp16 round, half2 stores
#pragma unroll
    for (int mf = 0; mf < 4; mf++) {
        const long r0g = m0 + mbase + mf * 16 + g;
#pragma unroll
        for (int nf = 0; nf < 4; nf++) {
            const int c = n0 + nbase + nf * 8 + t * 2;
            const float b0 = bias[c], b1 = bias[c + 1];
            float v0 = acc[mf][nf][0] + b0, v1 = acc[mf][nf][1] + b1;
            float v2 = acc[mf][nf][2] + b0, v3 = acc[mf][nf][3] + b1;
            __half2 h0 = __floats2half2_rn(v0 > 0.f ? v0 : 0.f, v1 > 0.f ? v1 : 0.f);
            __half2 h1 = __floats2half2_rn(v2 > 0.f ? v2 : 0.f, v3 > 0.f ? v3 : 0.f);
            *(__half2*)(out + r0g * D_ + c)       = h0;
            *(__half2*)(out + (r0g + 8) * D_ + c) = h1;
        }
    }
#undef HISSUE
}

// ---------------------------------------------------------------------------
// hgen80: mel[b,n,t] = dec @ W_gen^T + b_gen (transposed fp32 store), N = 80
//   tiles entirely past the valid prefix broadcast the constant mel column
// ---------------------------------------------------------------------------
#define HG_BTILE 10240         // 80 rows * 128 B
#define HG_STAGE (H_ATILE + HG_BTILE)
#define SMEM80 (2 * HG_STAGE + 1024)

__global__ void __launch_bounds__(256, 2) hgen80(
    const float* __restrict__ bias, float* __restrict__ mel)
{
    extern __shared__ char dsm[];
    const int tid  = threadIdx.x;
    const int warp = tid >> 5, lane = tid & 31;
    const int m0   = blockIdx.y * 128;

    {
        const int b = m0 / T_, t0 = m0 % T_;
        if (t0 >= g_tot[b]) {   // fully-invalid tile: broadcast constant column
            for (int idx = tid; idx < MELS_ * 32; idx += 256) {
                const int n  = idx >> 5;
                const int tt = (idx & 31) * 4;
                const float v = g_cmel[n];
                *(float4*)(mel + ((long)b * MELS_ + n) * T_ + t0 + tt) =
                    make_float4(v, v, v, v);
            }
            return;
        }
    }

    const uint32_t base = (smem_u32(dsm) + 1023) & ~1023u;
    const uint32_t Aoff[2] = { base, base + HG_STAGE };
    const uint32_t Boff[2] = { base + H_ATILE, base + HG_STAGE + H_ATILE };

    const int r0  = tid >> 3;
    const int seg = (tid & 7) * 16;
    const char* ap[4]; uint32_t adst[4];
    const char* bp[3]; uint32_t bdst[3]; int bok[3];
#pragma unroll
    for (int i = 0; i < 4; i++) {
        const int r = r0 + i * 32;
        ap[i]   = (const char*)g_dec + (long)(m0 + r) * D_ * 2;
        adst[i] = sw((uint32_t)(r * 128 + seg));
    }
#pragma unroll
    for (int i = 0; i < 3; i++) {
        const int r = r0 + i * 32;
        bok[i]  = (r < MELS_);
        bp[i]   = (const char*)g_wgenT + (long)(bok[i] ? r : 0) * D_ * 2;
        bdst[i] = sw((uint32_t)(r * 128 + seg));
    }

#define GISSUE(c, s) do {                                                     \
        const int kb = (c) * 128;                                             \
        _Pragma("unroll")                                                     \
        for (int i = 0; i < 4; i++) cpa16(Aoff[s] + adst[i], ap[i] + kb + seg, 16); \
        _Pragma("unroll")                                                     \
        for (int i = 0; i < 3; i++)                                           \
            if (bok[i]) cpa16(Boff[s] + bdst[i], bp[i] + kb + seg, 16);       \
        asm volatile("cp.async.commit_group;");                               \
    } while (0)

    const int mbase = (warp & 3) * 32;
    const int nbase = (warp >> 2) * 40;
    const int li  = lane & 7, grp = lane >> 3;
    const int ar  = (grp & 1) * 8 + li,  ak = (grp >> 1) * 16;
    const int br  = (grp >> 1) * 8 + li, bk = (grp & 1) * 16;
    const int g = lane >> 2, t = lane & 3;

    float acc[2][5][4] = {};

    GISSUE(0, 0);
#pragma unroll 1
    for (int c = 0; c < 8; c++) {
        if (c < 7) {
            GISSUE(c + 1, (c + 1) & 1);
            asm volatile("cp.async.wait_group 1;");
        } else {
            asm volatile("cp.async.wait_group 0;");
        }
        __syncthreads();
        const uint32_t Ab = Aoff[c & 1], Bb = Boff[c & 1];
#pragma unroll
        for (int kk = 0; kk < 4; kk++) {
            const int kb2 = kk * 32;
            uint32_t a[2][4], b[5][2];
#pragma unroll
            for (int mf = 0; mf < 2; mf++) {
                uint32_t o = (uint32_t)((mbase + mf * 16 + ar) * 128 + kb2 + ak);
                ldm4(a[mf], Ab + sw(o));
            }
#pragma unroll
            for (int nfp = 0; nfp < 2; nfp++) {
                uint32_t o = (uint32_t)((nbase + nfp * 16 + br) * 128 + kb2 + bk);
                uint32_t r[4]; ldm4(r, Bb + sw(o));
                b[nfp * 2][0] = r[0]; b[nfp * 2][1] = r[1];
                b[nfp * 2 + 1][0] = r[2]; b[nfp * 2 + 1][1] = r[3];
            }
            {   // last n-frag (rows nbase+32..39) via x2
                uint32_t o = (uint32_t)((nbase + 32 + li) * 128 + kb2 + (grp & 1) * 16);
                ldm2(b[4], Bb + sw(o));
            }
#pragma unroll
            for (int mf = 0; mf < 2; mf++)
#pragma unroll
                for (int nf = 0; nf < 5; nf++)
                    mma_f16(acc[mf][nf], a[mf], b[nf]);
        }
        __syncthreads();
    }

    // transposed epilogue: mel[b, n, t]
#pragma unroll
    for (int mf = 0; mf < 2; mf++) {
        const int rg = m0 + mbase + mf * 16 + g;
        const int b  = rg / T_;
        const int tt = rg - b * T_;
#pragma unroll
        for (int nf = 0; nf < 5; nf++) {
            const int n = nbase + nf * 8 + t * 2;
            const float b0 = bias[n], b1 = bias[n + 1];
            float* p0 = mel + ((long)b * MELS_ + n) * T_;
            float* p1 = p0 + T_;
            p0[tt]     = acc[mf][nf][0] + b0;
            p1[tt]     = acc[mf][nf][1] + b1;
            p0[tt + 8] = acc[mf][nf][2] + b0;
            p1[tt + 8] = acc[mf][nf][3] + b1;
        }
    }
#undef GISSUE
}

// ---------------------------------------------------------------------------
// duration head (reads fp16 enc)
// ---------------------------------------------------------------------------
__global__ void dur_kernel(const float* __restrict__ Wd, const float* __restrict__ bd,
                           float* __restrict__ out)
{
    const int m    = blockIdx.x * 8 + threadIdx.y;
    const int lane = threadIdx.x;
    float s = 0.f;
    for (int k = lane; k < D_; k += 32)
        s += __half2float(g_enc[(long)m * D_ + k]) * Wd[k];
#pragma unroll
    for (int o = 16; o; o >>= 1) s += __shfl_xor_sync(0xffffffffu, s, o);
    if (lane == 0) out[m] = s + bd[0];
}

// ---------------------------------------------------------------------------
extern "C" void kernel_launch(void* const* d_in, const int* in_sizes, int n_in,
                              void* d_out, int out_size)
{
    const int* src = (const int*)d_in[0];
    const int* dur = (const int*)d_in[1];
    int p = 2;
    if (p < n_in && in_sizes[2] <= 4) p = 3;  // skip scalar T if materialized
    const float* emb   = (const float*)d_in[p + 0];
    const float* pos   = (const float*)d_in[p + 1];
    const float* W_enc = (const float*)d_in[p + 2];
    const float* b_enc = (const float*)d_in[p + 3];
    const float* W_dur = (const float*)d_in[p + 4];
    const float* b_dur = (const float*)d_in[p + 5];
    const float* W_dec = (const float*)d_in[p + 6];
    const float* b_dec = (const float*)d_in[p + 7];
    const float* W_gen = (const float*)d_in[p + 8];
    const float* b_gen = (const float*)d_in[p + 9];

    float* mel  = (float*)d_out;                         // [B, MELS, T]
    float* durp = (float*)d_out + (long)B_ * MELS_ * T_; // [B, L]

    static bool attr_done = false;
    if (!attr_done) {
        cudaFuncSetAttribute(hgemm512, cudaFuncAttributeMaxDynamicSharedMemorySize, SMEM512);
        cudaFuncSetAttribute(hgen80,   cudaFuncAttributeMaxDynamicSharedMemorySize, SMEM80);
        attr_done = true;
    }

    __half *d_wencT, *d_wdecT, *d_wgenT, *d_x, *d_enc, *d_decb;
    int *d_aidx, *d_tot;
    cudaGetSymbolAddress((void**)&d_wencT, g_wencT);
    cudaGetSymbolAddress((void**)&d_wdecT, g_wdecT);
    cudaGetSymbolAddress((void**)&d_wgenT, g_wgenT);
    cudaGetSymbolAddress((void**)&d_x,     g_x);
    cudaGetSymbolAddress((void**)&d_enc,   g_enc);
    cudaGetSymbolAddress((void**)&d_decb,  g_dec);
    cudaGetSymbolAddress((void**)&d_aidx,  g_aidx);
    cudaGetSymbolAddress((void**)&d_tot,   g_tot);

    transpose_f16<<<dim3(16, 16), dim3(32, 8)>>>(W_enc, d_wencT, D_, D_);
    transpose_f16<<<dim3(16, 16), dim3(32, 8)>>>(W_dec, d_wdecT, D_, D_);
    transpose_f16<<<dim3(3, 16),  dim3(32, 8)>>>(W_gen, d_wgenT, D_, MELS_);
    prep_x_kernel<<<M_ENC * (D_ / 4) / 256, 256>>>(src, emb, pos);
    tok_kernel<<<B_, 256>>>(dur);
    cmel_kernel<<<1, 128>>>(b_dec, W_gen, b_gen);

    hgemm512<<<dim3(D_ / 128, M_ENC / 128), 256, SMEM512>>>(
        d_x, nullptr, nullptr, d_wencT, b_enc, d_enc);
    dur_kernel<<<M_ENC / 8, dim3(32, 8)>>>(W_dur, b_dur, durp);
    hgemm512<<<dim3(D_ / 128, M_DEC / 128), 256, SMEM512>>>(
        d_enc, d_aidx, d_tot, d_wdecT, b_dec, d_decb);
    hgen80<<<dim3(1, M_DEC / 128), 256, SMEM80>>>(b_gen, mel);
}

// round 6
// speedup vs baseline: 14.5437x; 1.4392x over previous
#include <cuda_runtime.h>
#include <cuda_fp16.h>
#include <cstdint>

#define B_    16
#define L_    256
#define D_    512
#define MELS_ 80
#define T_    3072
#define M_ENC (B_ * L_)   // 4096
#define M_DEC (B_ * T_)   // 49152
#define MT_ST 4160        // melT row stride (tokens 0..4095 + constant col 4096)

// Scratch (__device__ globals; no allocation allowed)
__device__ __half g_x    [M_ENC * D_];   // fp16(emb[src]+pos)
__device__ __half g_enc  [M_ENC * D_];   // fp16(relu(enc))
__device__ __half g_dect [M_ENC * D_];   // fp16(relu(dec)) per TOKEN
__device__ int    g_aidx [M_DEC];        // global token index per frame, M_ENC = invalid
__device__ float  g_melT [MELS_ * MT_ST];// melT[n][token]; col M_ENC = constant
__device__ __half g_wencT[D_ * D_];      // fp16 W^T  [N][K]
__device__ __half g_wdecT[D_ * D_];
__device__ __half g_wgenT[MELS_ * D_];

// ---------------------------------------------------------------------------
__device__ __forceinline__ uint32_t smem_u32(const void* p) {
    return (uint32_t)__cvta_generic_to_shared(p);
}
__device__ __forceinline__ void cpa16(uint32_t dst, const void* src, int srcsize) {
    asm volatile("cp.async.cg.shared.global [%0], [%1], 16, %2;"
                 :: "r"(dst), "l"(src), "r"(srcsize));
}
__device__ __forceinline__ uint32_t sw(uint32_t o) { return o ^ ((o >> 3) & 0x70); }

__device__ __forceinline__ void ldm4(uint32_t* r, uint32_t addr) {
    asm volatile("ldmatrix.sync.aligned.m8n8.x4.shared.b16 {%0,%1,%2,%3}, [%4];"
                 : "=r"(r[0]), "=r"(r[1]), "=r"(r[2]), "=r"(r[3]) : "r"(addr));
}
__device__ __forceinline__ void ldm2(uint32_t* r, uint32_t addr) {
    asm volatile("ldmatrix.sync.aligned.m8n8.x2.shared.b16 {%0,%1}, [%2];"
                 : "=r"(r[0]), "=r"(r[1]) : "r"(addr));
}
__device__ __forceinline__ void mma_f16(float* d, const uint32_t* a, const uint32_t* b) {
    asm volatile(
        "mma.sync.aligned.m16n8k16.row.col.f32.f16.f16.f32 "
        "{%0,%1,%2,%3},{%4,%5,%6,%7},{%8,%9},{%0,%1,%2,%3};"
        : "+f"(d[0]), "+f"(d[1]), "+f"(d[2]), "+f"(d[3])
        : "r"(a[0]), "r"(a[1]), "r"(a[2]), "r"(a[3]), "r"(b[0]), "r"(b[1]));
}

// ---------------------------------------------------------------------------
// prep: transpose + fp16 round for the two 512x512 weights (blockIdx.z picks)
// ---------------------------------------------------------------------------
__global__ void transpose2_f16(const float* __restrict__ W0, const float* __restrict__ W1) {
    __shared__ float tile[32][33];
    const float* src = blockIdx.z ? W1 : W0;
    __half* dst = blockIdx.z ? g_wdecT : g_wencT;
    const int c0 = blockIdx.x * 32, r0 = blockIdx.y * 32;
#pragma unroll
    for (int i = 0; i < 4; i++)
        tile[threadIdx.y + i * 8][threadIdx.x] =
            src[(r0 + threadIdx.y + i * 8) * D_ + c0 + threadIdx.x];
    __syncthreads();
#pragma unroll
    for (int i = 0; i < 4; i++)
        dst[(long)(c0 + threadIdx.y + i * 8) * D_ + r0 + threadIdx.x] =
            __float2half_rn(tile[threadIdx.x][threadIdx.y + i * 8]);
}

__global__ void transpose_gen_f16(const float* __restrict__ src) {
    __shared__ float tile[32][33];
    const int c0 = blockIdx.x * 32, r0 = blockIdx.y * 32;   // c over MELS, r over D
#pragma unroll
    for (int i = 0; i < 4; i++) {
        int r = r0 + threadIdx.y + i * 8, c = c0 + threadIdx.x;
        if (c < MELS_) tile[threadIdx.y + i * 8][threadIdx.x] = src[r * MELS_ + c];
    }
    __syncthreads();
#pragma unroll
    for (int i = 0; i < 4; i++) {
        int c = c0 + threadIdx.y + i * 8, r = r0 + threadIdx.x;
        if (c < MELS_)
            g_wgenT[(long)c * D_ + r] = __float2half_rn(tile[threadIdx.x][threadIdx.y + i * 8]);
    }
}

// prep: g_x[m][d] = fp16(emb[src[m]][d] + pos[m % L][d])
__global__ void prep_x_kernel(const int* __restrict__ src, const float* __restrict__ emb,
                              const float* __restrict__ pos) {
    const long idx = (long)blockIdx.x * 256 + threadIdx.x;   // float4 index
    const int  m   = (int)(idx >> 7);
    const int  d4  = (int)(idx & 127) * 4;
    float4 e = *(const float4*)(emb + (long)src[m] * D_ + d4);
    float4 p = *(const float4*)(pos + (long)(m & (L_ - 1)) * D_ + d4);
    __half2 h0 = __floats2half2_rn(e.x + p.x, e.y + p.y);
    __half2 h1 = __floats2half2_rn(e.z + p.z, e.w + p.w);
    uint2 u = make_uint2(*(uint32_t*)&h0, *(uint32_t*)&h1);
    *(uint2*)(g_x + idx * 4) = u;
}

// constant mel column (fp32):  melT[n][M_ENC] = relu(b_dec) . W_gen[:, n] + b_gen[n]
__global__ void cmel_kernel(const float* __restrict__ b_dec,
                            const float* __restrict__ W_gen,
                            const float* __restrict__ b_gen) {
    __shared__ float rd[D_];
    for (int k = threadIdx.x; k < D_; k += blockDim.x) {
        float v = b_dec[k]; rd[k] = v > 0.f ? v : 0.f;
    }
    __syncthreads();
    const int n = threadIdx.x;
    if (n < MELS_) {
        float s = b_gen[n];
        for (int k = 0; k < D_; k++) s += rd[k] * W_gen[k * MELS_ + n];
        g_melT[n * MT_ST + M_ENC] = s;
    }
}

// ---------------------------------------------------------------------------
// tok: per-batch inclusive scan + per-frame searchsorted
//   g_aidx[b*T+t] = global token index (b*L + tok), or M_ENC if past total dur
// ---------------------------------------------------------------------------
__global__ void tok_kernel(const int* __restrict__ dur) {
    __shared__ int csum[L_];
    const int b = blockIdx.x, tid = threadIdx.x;
    csum[tid] = dur[b * L_ + tid];
    __syncthreads();
    for (int off = 1; off < L_; off <<= 1) {
        int x = (tid >= off) ? csum[tid - off] : 0;
        __syncthreads();
        csum[tid] += x;
        __syncthreads();
    }
    for (int t = tid; t < T_; t += blockDim.x) {
        int lo = 0, hi = L_;
        while (lo < hi) {
            int mid = (lo + hi) >> 1;
            if (csum[mid] > t) hi = mid; else lo = mid + 1;
        }
        g_aidx[b * T_ + t] = (lo < L_) ? (b * L_ + lo) : M_ENC;
    }
}

// ---------------------------------------------------------------------------
// hgemm512: out = fp16(relu(A @ Bt^T + bias)),  M = 4096, K = N = 512, fp16 in
//   128x128 CTA tile, BK = 64 halves (128 B), double-buffered cp.async
//   8 warps (2m x 4n), ldmatrix fragments, mma.m16n8k16
// ---------------------------------------------------------------------------
#define H_ATILE 16384          // 128 rows * 128 B
#define H_STAGE (2 * H_ATILE)  // A + B
#define SMEM512 (2 * H_STAGE + 1024)

__global__ void __launch_bounds__(256, 2) hgemm512(
    const __half* __restrict__ A, const __half* __restrict__ Bt,
    const float* __restrict__ bias, __half* __restrict__ out)
{
    extern __shared__ char dsm[];
    const int tid  = threadIdx.x;
    const int warp = tid >> 5, lane = tid & 31;
    const int m0   = blockIdx.y * 128, n0 = blockIdx.x * 128;

    const uint32_t base = (smem_u32(dsm) + 1023) & ~1023u;
    const uint32_t Aoff[2] = { base, base + H_STAGE };
    const uint32_t Boff[2] = { base + H_ATILE, base + H_STAGE + H_ATILE };

    // loads: 4 A rows + 4 B rows per thread, 16B each per stage
    const int r0  = tid >> 3;
    const int seg = (tid & 7) * 16;
    const char* ap[4];
    const char* bp[4];
    uint32_t dst[4];
#pragma unroll
    for (int i = 0; i < 4; i++) {
        const int r = r0 + i * 32;
        ap[i]  = (const char*)A  + (long)(m0 + r) * D_ * 2;
        bp[i]  = (const char*)Bt + (long)(n0 + r) * D_ * 2;
        dst[i] = sw((uint32_t)(r * 128 + seg));
    }

#define HISSUE(c, s) do {                                                     \
        const int kb = (c) * 128;                                             \
        _Pragma("unroll")                                                     \
        for (int i = 0; i < 4; i++) cpa16(Aoff[s] + dst[i], ap[i] + kb + seg, 16); \
        _Pragma("unroll")                                                     \
        for (int i = 0; i < 4; i++) cpa16(Boff[s] + dst[i], bp[i] + kb + seg, 16); \
        asm volatile("cp.async.commit_group;");                               \
    } while (0)

    const int mbase = (warp & 1) * 64;
    const int nbase = (warp >> 1) * 32;
    const int li  = lane & 7, grp = lane >> 3;
    const int ar  = (grp & 1) * 8 + li,  ak = (grp >> 1) * 16;   // A ldmatrix
    const int br  = (grp >> 1) * 8 + li, bk = (grp & 1) * 16;    // B ldmatrix
    const int g = lane >> 2, t = lane & 3;

    float acc[4][4][4] = {};

    HISSUE(0, 0);
#pragma unroll 1
    for (int c = 0; c < 8; c++) {
        if (c < 7) {
            HISSUE(c + 1, (c + 1) & 1);
            asm volatile("cp.async.wait_group 1;");
        } else {
            asm volatile("cp.async.wait_group 0;");
        }
        __syncthreads();
        const uint32_t Ab = Aoff[c & 1], Bb = Boff[c & 1];
#pragma unroll
        for (int kk = 0; kk < 4; kk++) {
            const int kb2 = kk * 32;
            uint32_t a[4][4], b[4][2];
#pragma unroll
            for (int mf = 0; mf < 4; mf++) {
                uint32_t o = (uint32_t)((mbase + mf * 16 + ar) * 128 + kb2 + ak);
                ldm4(a[mf], Ab + sw(o));
            }
#pragma unroll
            for (int nfp = 0; nfp < 2; nfp++) {
                uint32_t o = (uint32_t)((nbase + nfp * 16 + br) * 128 + kb2 + bk);
                uint32_t r[4]; ldm4(r, Bb + sw(o));
                b[nfp * 2][0] = r[0]; b[nfp * 2][1] = r[1];
                b[nfp * 2 + 1][0] = r[2]; b[nfp * 2 + 1][1] = r[3];
            }
#pragma unroll
            for (int mf = 0; mf < 4; mf++)
#pragma unroll
                for (int nf = 0; nf < 4; nf++)
                    mma_f16(acc[mf][nf], a[mf], b[nf]);
        }
        __syncthreads();
    }

    // epilogue: bias + relu + fp16 round, half2 stores
#pragma unroll
    for (int mf = 0; mf < 4; mf++) {
        const long r0g = m0 + mbase + mf * 16 + g;
#pragma unroll
        for (int nf = 0; nf < 4; nf++) {
            const int c = n0 + nbase + nf * 8 + t * 2;
            const float b0 = bias[c], b1 = bias[c + 1];
            float v0 = acc[mf][nf][0] + b0, v1 = acc[mf][nf][1] + b1;
            float v2 = acc[mf][nf][2] + b0, v3 = acc[mf][nf][3] + b1;
            __half2 h0 = __floats2half2_rn(v0 > 0.f ? v0 : 0.f, v1 > 0.f ? v1 : 0.f);
            __half2 h1 = __floats2half2_rn(v2 > 0.f ? v2 : 0.f, v3 > 0.f ? v3 : 0.f);
            *(__half2*)(out + r0g * D_ + c)       = h0;
            *(__half2*)(out + (r0g + 8) * D_ + c) = h1;
        }
    }
#undef HISSUE
}

// ---------------------------------------------------------------------------
// genT: melT[n][token] = dec_tok @ W_gen^T + b_gen   (M = 4096 tokens, N = 80)
// ---------------------------------------------------------------------------
#define HG_BTILE 10240         // 80 rows * 128 B
#define HG_STAGE (H_ATILE + HG_BTILE)
#define SMEM80 (2 * HG_STAGE + 1024)

__global__ void __launch_bounds__(256, 2) genT_kernel(const float* __restrict__ bias)
{
    extern __shared__ char dsm[];
    const int tid  = threadIdx.x;
    const int warp = tid >> 5, lane = tid & 31;
    const int m0   = blockIdx.y * 128;

    const uint32_t base = (smem_u32(dsm) + 1023) & ~1023u;
    const uint32_t Aoff[2] = { base, base + HG_STAGE };
    const uint32_t Boff[2] = { base + H_ATILE, base + HG_STAGE + H_ATILE };

    const int r0  = tid >> 3;
    const int seg = (tid & 7) * 16;
    const char* ap[4]; uint32_t adst[4];
    const char* bp[3]; uint32_t bdst[3]; int bok[3];
#pragma unroll
    for (int i = 0; i < 4; i++) {
        const int r = r0 + i * 32;
        ap[i]   = (const char*)g_dect + (long)(m0 + r) * D_ * 2;
        adst[i] = sw((uint32_t)(r * 128 + seg));
    }
#pragma unroll
    for (int i = 0; i < 3; i++) {
        const int r = r0 + i * 32;
        bok[i]  = (r < MELS_);
        bp[i]   = (const char*)g_wgenT + (long)(bok[i] ? r : 0) * D_ * 2;
        bdst[i] = sw((uint32_t)(r * 128 + seg));
    }

#define GISSUE(c, s) do {                                                     \
        const int kb = (c) * 128;                                             \
        _Pragma("unroll")                                                     \
        for (int i = 0; i < 4; i++) cpa16(Aoff[s] + adst[i], ap[i] + kb + seg, 16); \
        _Pragma("unroll")                                                     \
        for (int i = 0; i < 3; i++)                                           \
            if (bok[i]) cpa16(Boff[s] + bdst[i], bp[i] + kb + seg, 16);       \
        asm volatile("cp.async.commit_group;");                               \
    } while (0)

    const int mbase = (warp & 3) * 32;
    const int nbase = (warp >> 2) * 40;
    const int li  = lane & 7, grp = lane >> 3;
    const int ar  = (grp & 1) * 8 + li,  ak = (grp >> 1) * 16;
    const int br  = (grp >> 1) * 8 + li, bk = (grp & 1) * 16;
    const int g = lane >> 2, t = lane & 3;

    float acc[2][5][4] = {};

    GISSUE(0, 0);
#pragma unroll 1
    for (int c = 0; c < 8; c++) {
        if (c < 7) {
            GISSUE(c + 1, (c + 1) & 1);
            asm volatile("cp.async.wait_group 1;");
        } else {
            asm volatile("cp.async.wait_group 0;");
        }
        __syncthreads();
        const uint32_t Ab = Aoff[c & 1], Bb = Boff[c & 1];
#pragma unroll
        for (int kk = 0; kk < 4; kk++) {
            const int kb2 = kk * 32;
            uint32_t a[2][4], b[5][2];
#pragma unroll
            for (int mf = 0; mf < 2; mf++) {
                uint32_t o = (uint32_t)((mbase + mf * 16 + ar) * 128 + kb2 + ak);
                ldm4(a[mf], Ab + sw(o));
            }
#pragma unroll
            for (int nfp = 0; nfp < 2; nfp++) {
                uint32_t o = (uint32_t)((nbase + nfp * 16 + br) * 128 + kb2 + bk);
                uint32_t r[4]; ldm4(r, Bb + sw(o));
                b[nfp * 2][0] = r[0]; b[nfp * 2][1] = r[1];
                b[nfp * 2 + 1][0] = r[2]; b[nfp * 2 + 1][1] = r[3];
            }
            {   // last n-frag (rows nbase+32..39) via x2
                uint32_t o = (uint32_t)((nbase + 32 + li) * 128 + kb2 + (grp & 1) * 16);
                ldm2(b[4], Bb + sw(o));
            }
#pragma unroll
            for (int mf = 0; mf < 2; mf++)
#pragma unroll
                for (int nf = 0; nf < 5; nf++)
                    mma_f16(acc[mf][nf], a[mf], b[nf]);
        }
        __syncthreads();
    }

    // transposed epilogue: melT[n][token]
#pragma unroll
    for (int mf = 0; mf < 2; mf++) {
        const int tok = m0 + mbase + mf * 16 + g;
#pragma unroll
        for (int nf = 0; nf < 5; nf++) {
            const int n = nbase + nf * 8 + t * 2;
            const float b0 = bias[n], b1 = bias[n + 1];
            float* p0 = g_melT + (long)n * MT_ST;
            float* p1 = p0 + MT_ST;
            p0[tok]     = acc[mf][nf][0] + b0;
            p1[tok]     = acc[mf][nf][1] + b1;
            p0[tok + 8] = acc[mf][nf][2] + b0;
            p1[tok + 8] = acc[mf][nf][3] + b1;
        }
    }
#undef GISSUE
}

// ---------------------------------------------------------------------------
// expand: mel[b, n, t] = melT[n][ aidx[b, t] ]   (pure bandwidth)
// ---------------------------------------------------------------------------
__global__ void expand_kernel(float* __restrict__ mel) {
    const int b   = blockIdx.y;
    const int t0  = blockIdx.x * 256;
    const int tid = threadIdx.x;
    const int tok = g_aidx[b * T_ + t0 + tid];
    float* base = mel + (long)b * MELS_ * T_ + t0 + tid;
    const float* mt = g_melT + tok;
#pragma unroll 8
    for (int n = 0; n < MELS_; n++)
        base[(long)n * T_] = mt[(long)n * MT_ST];
}

// ---------------------------------------------------------------------------
// duration head (reads fp16 enc)
// ---------------------------------------------------------------------------
__global__ void dur_kernel(const float* __restrict__ Wd, const float* __restrict__ bd,
                           float* __restrict__ out)
{
    const int m    = blockIdx.x * 8 + threadIdx.y;
    const int lane = threadIdx.x;
    float s = 0.f;
    for (int k = lane; k < D_; k += 32)
        s += __half2float(g_enc[(long)m * D_ + k]) * Wd[k];
#pragma unroll
    for (int o = 16; o; o >>= 1) s += __shfl_xor_sync(0xffffffffu, s, o);
    if (lane == 0) out[m] = s + bd[0];
}

// ---------------------------------------------------------------------------
extern "C" void kernel_launch(void* const* d_in, const int* in_sizes, int n_in,
                              void* d_out, int out_size)
{
    const int* src = (const int*)d_in[0];
    const int* dur = (const int*)d_in[1];
    int p = 2;
    if (p < n_in && in_sizes[2] <= 4) p = 3;  // skip scalar T if materialized
    const float* emb   = (const float*)d_in[p + 0];
    const float* pos   = (const float*)d_in[p + 1];
    const float* W_enc = (const float*)d_in[p + 2];
    const float* b_enc = (const float*)d_in[p + 3];
    const float* W_dur = (const float*)d_in[p + 4];
    const float* b_dur = (const float*)d_in[p + 5];
    const float* W_dec = (const float*)d_in[p + 6];
    const float* b_dec = (const float*)d_in[p + 7];
    const float* W_gen = (const float*)d_in[p + 8];
    const float* b_gen = (const float*)d_in[p + 9];

    float* mel  = (float*)d_out;                         // [B, MELS, T]
    float* durp = (float*)d_out + (long)B_ * MELS_ * T_; // [B, L]

    static bool attr_done = false;
    if (!attr_done) {
        cudaFuncSetAttribute(hgemm512,    cudaFuncAttributeMaxDynamicSharedMemorySize, SMEM512);
        cudaFuncSetAttribute(genT_kernel, cudaFuncAttributeMaxDynamicSharedMemorySize, SMEM80);
        attr_done = true;
    }

    __half *d_wencT, *d_wdecT, *d_x, *d_enc, *d_dect;
    cudaGetSymbolAddress((void**)&d_wencT, g_wencT);
    cudaGetSymbolAddress((void**)&d_wdecT, g_wdecT);
    cudaGetSymbolAddress((void**)&d_x,     g_x);
    cudaGetSymbolAddress((void**)&d_enc,   g_enc);
    cudaGetSymbolAddress((void**)&d_dect,  g_dect);

    transpose2_f16<<<dim3(16, 16, 2), dim3(32, 8)>>>(W_enc, W_dec);
    transpose_gen_f16<<<dim3(3, 16), dim3(32, 8)>>>(W_gen);
    prep_x_kernel<<<M_ENC * (D_ / 4) / 256, 256>>>(src, emb, pos);
    tok_kernel<<<B_, 256>>>(dur);
    cmel_kernel<<<1, 128>>>(b_dec, W_gen, b_gen);

    hgemm512<<<dim3(D_ / 128, M_ENC / 128), 256, SMEM512>>>(d_x, d_wencT, b_enc, d_enc);
    dur_kernel<<<M_ENC / 8, dim3(32, 8)>>>(W_dur, b_dur, durp);
    hgemm512<<<dim3(D_ / 128, M_ENC / 128), 256, SMEM512>>>(d_enc, d_wdecT, b_dec, d_dect);
    genT_kernel<<<dim3(1, M_ENC / 128), 256, SMEM80>>>(b_gen);
    expand_kernel<<<dim3(T_ / 256, B_), 256>>>(mel);
}